// round 4
// baseline (speedup 1.0000x reference)
#include <cuda_runtime.h>
#include <math.h>

#define BB 4096
#define SS 200
#define DD 64
#define VV 100000
#define ROWF 24   // floats per precomputed row: g[5], q[18], pad

// Static device scratch (allocation-free per harness rules)
__device__ float g_proj[(size_t)VV * ROWF];  // [v]: exp(tanh(att)) x5, emb.W_j x18
__device__ float g_loss[BB];

__device__ __forceinline__ float fast_tanh(float x) {
    float ax = fabsf(x);
    float t  = __expf(-2.0f * ax);
    float r  = __fdividef(1.0f - t, 1.0f + t);
    return copysignf(r, x);
}

__device__ __forceinline__ unsigned long long pack2(float lo, float hi) {
    unsigned long long r;
    asm("mov.b64 %0, {%1, %2};" : "=l"(r) : "f"(lo), "f"(hi));
    return r;
}
__device__ __forceinline__ void unpack2(unsigned long long v, float& lo, float& hi) {
    asm("mov.b64 {%0, %1}, %2;" : "=f"(lo), "=f"(hi) : "l"(v));
}
__device__ __forceinline__ unsigned long long ffma2(unsigned long long a,
                                                    unsigned long long b,
                                                    unsigned long long c) {
    unsigned long long d;
    asm("fma.rn.f32x2 %0, %1, %2, %3;" : "=l"(d) : "l"(a), "l"(b), "l"(c));
    return d;
}

// ---------------------------------------------------------------------------
// Kernel 1: per-vocab precompute.
//   For each v: 23 dot products of emb_table[v] (64-d) against
//   U = [att_w(5) ; W0(2);W1(4);W2(4);W3(2);W4(6)] (18).
//   Store row: [exp(tanh(att_dot+b)) x5, q x18, 0].
//   Weights transposed in smem as (d-pair, j, half) so inner loop is
//   LDS.128 (4 weights) + 2x fma.rn.f32x2.
// ---------------------------------------------------------------------------
__global__ void __launch_bounds__(128)
proj_kernel(const float* __restrict__ emb,
            const float* __restrict__ aw,  const float* __restrict__ ab,
            const float* __restrict__ W0,  const float* __restrict__ W1,
            const float* __restrict__ W2,  const float* __restrict__ W3,
            const float* __restrict__ W4) {
    __shared__ float swp[32 * 48];   // [dp][j*2+h], d = 2*dp+h, j in 0..23 (23 = pad)
    __shared__ float sab[5];
    const int tid = threadIdx.x;

    for (int e = tid; e < 32 * 48; e += blockDim.x) {
        int dp = e / 48, r = e % 48;
        int j = r >> 1, h = r & 1;
        int d = dp * 2 + h;
        float val = 0.0f;
        if (j < 5) {
            val = aw[j * 64 + d];
        } else if (j < 23) {
            int jq = j - 5;
            const float* Wsrc; int row;
            if      (jq < 2)  { Wsrc = W0; row = jq;      }
            else if (jq < 6)  { Wsrc = W1; row = jq - 2;  }
            else if (jq < 10) { Wsrc = W2; row = jq - 6;  }
            else if (jq < 12) { Wsrc = W3; row = jq - 10; }
            else              { Wsrc = W4; row = jq - 12; }
            val = Wsrc[row * 64 + d];
        }
        swp[e] = val;
    }
    if (tid < 5) sab[tid] = ab[tid];
    __syncthreads();

    const int v = blockIdx.x * blockDim.x + tid;
    if (v >= VV) return;

    unsigned long long acc[23];
#pragma unroll
    for (int j = 0; j < 23; j++) acc[j] = 0ull;

    const float4* row = (const float4*)(emb + (size_t)v * DD);
#pragma unroll
    for (int i = 0; i < 16; i++) {
        float4 ev = row[i];
        unsigned long long e01 = pack2(ev.x, ev.y);
        unsigned long long e23 = pack2(ev.z, ev.w);
        const float4* w0 = (const float4*)(swp + (2 * i) * 48);
        const float4* w1 = (const float4*)(swp + (2 * i + 1) * 48);
#pragma unroll
        for (int jj = 0; jj < 12; jj++) {
            float4 wa = w0[jj];
            acc[2 * jj] = ffma2(pack2(wa.x, wa.y), e01, acc[2 * jj]);
            if (jj < 11)
                acc[2 * jj + 1] = ffma2(pack2(wa.z, wa.w), e01, acc[2 * jj + 1]);
        }
#pragma unroll
        for (int jj = 0; jj < 12; jj++) {
            float4 wb = w1[jj];
            acc[2 * jj] = ffma2(pack2(wb.x, wb.y), e23, acc[2 * jj]);
            if (jj < 11)
                acc[2 * jj + 1] = ffma2(pack2(wb.z, wb.w), e23, acc[2 * jj + 1]);
        }
    }

    float res[23];
#pragma unroll
    for (int j = 0; j < 23; j++) {
        float lo, hi;
        unpack2(acc[j], lo, hi);
        res[j] = lo + hi;
    }

    float o[24];
#pragma unroll
    for (int k = 0; k < 5; k++)
        o[k] = __expf(fast_tanh(res[k] + sab[k]));
#pragma unroll
    for (int j = 0; j < 18; j++) o[5 + j] = res[5 + j];
    o[23] = 0.0f;

    float4* op = (float4*)(g_proj + (size_t)v * ROWF);
#pragma unroll
    for (int i = 0; i < 6; i++)
        op[i] = make_float4(o[4 * i], o[4 * i + 1], o[4 * i + 2], o[4 * i + 3]);
}

// ---------------------------------------------------------------------------
// Kernel 2: main fused kernel. One warp per batch element.
//   Lane handles s = lane + 32*i, i in 0..6. Per s: gather 96B precomputed
//   row, accumulate lsum[5] and acc[18]. Warp-reduce 23 values, then
//   per-group softmax + loss in the epilogue.
//   j -> attr map: [0,0, 1,1,1,1, 2,2,2,2, 3,3, 4,4,4,4,4,4]
// ---------------------------------------------------------------------------
__global__ void __launch_bounds__(128)
main_kernel(const int*   __restrict__ x,
            const float* __restrict__ y,
            float* __restrict__ out) {
    const int lane = threadIdx.x & 31;
    const int warp = threadIdx.x >> 5;
    const int b    = blockIdx.x * 4 + warp;

    const int* xb = x + b * SS;
    int idx[7];
#pragma unroll
    for (int i = 0; i < 7; i++) {
        int s = i * 32 + lane;
        idx[i] = (s < SS) ? xb[s] : -1;
    }

    float ls[5]  = {0.f, 0.f, 0.f, 0.f, 0.f};
    float acc[18];
#pragma unroll
    for (int j = 0; j < 18; j++) acc[j] = 0.0f;

#pragma unroll
    for (int i = 0; i < 7; i++) {
        if (idx[i] >= 0) {
            const float4* r = (const float4*)(g_proj + (size_t)idx[i] * ROWF);
            float4 r0 = r[0];  // g0 g1 g2 g3
            float4 r1 = r[1];  // g4 q0 q1 q2
            float4 r2 = r[2];  // q3 q4 q5 q6
            float4 r3 = r[3];  // q7 q8 q9 q10
            float4 r4 = r[4];  // q11 q12 q13 q14
            float4 r5 = r[5];  // q15 q16 q17 pad
            ls[0] += r0.x; ls[1] += r0.y; ls[2] += r0.z; ls[3] += r0.w; ls[4] += r1.x;
            // attr 0 (k=0): q0,q1
            acc[0]  = fmaf(r0.x, r1.y, acc[0]);
            acc[1]  = fmaf(r0.x, r1.z, acc[1]);
            // attr 1 (k=1): q2..q5
            acc[2]  = fmaf(r0.y, r1.w, acc[2]);
            acc[3]  = fmaf(r0.y, r2.x, acc[3]);
            acc[4]  = fmaf(r0.y, r2.y, acc[4]);
            acc[5]  = fmaf(r0.y, r2.z, acc[5]);
            // attr 2 (k=2): q6..q9
            acc[6]  = fmaf(r0.z, r2.w, acc[6]);
            acc[7]  = fmaf(r0.z, r3.x, acc[7]);
            acc[8]  = fmaf(r0.z, r3.y, acc[8]);
            acc[9]  = fmaf(r0.z, r3.z, acc[9]);
            // attr 3 (k=3): q10,q11
            acc[10] = fmaf(r0.w, r3.w, acc[10]);
            acc[11] = fmaf(r0.w, r4.x, acc[11]);
            // attr 4 (k=4): q12..q17
            acc[12] = fmaf(r1.x, r4.y, acc[12]);
            acc[13] = fmaf(r1.x, r4.z, acc[13]);
            acc[14] = fmaf(r1.x, r4.w, acc[14]);
            acc[15] = fmaf(r1.x, r5.x, acc[15]);
            acc[16] = fmaf(r1.x, r5.y, acc[16]);
            acc[17] = fmaf(r1.x, r5.z, acc[17]);
        }
    }

    // Warp reductions (all lanes end with full sums)
#pragma unroll
    for (int k = 0; k < 5; k++) {
#pragma unroll
        for (int o = 16; o > 0; o >>= 1)
            ls[k] += __shfl_xor_sync(0xffffffffu, ls[k], o);
    }
#pragma unroll
    for (int j = 0; j < 18; j++) {
#pragma unroll
        for (int o = 16; o > 0; o >>= 1)
            acc[j] += __shfl_xor_sync(0xffffffffu, acc[j], o);
    }

    float inv[5];
#pragma unroll
    for (int k = 0; k < 5; k++) inv[k] = 1.0f / ls[k];

    const int kmap[18] = {0,0, 1,1,1,1, 2,2,2,2, 3,3, 4,4,4,4,4,4};
    float outv[18];
#pragma unroll
    for (int j = 0; j < 18; j++) outv[j] = acc[j] * inv[kmap[j]];

    // Per-group softmax + cross-entropy loss (uniform across lanes)
    const float* yb = y + b * 18;
    const int AL[5] = {2, 4, 4, 2, 6};
    float loss = 0.0f;
    float logits[18];
    int base = 0;
#pragma unroll
    for (int i = 0; i < 5; i++) {
        const int L = AL[i];
        float m = outv[base];
#pragma unroll
        for (int jj = 1; jj < L; jj++) m = fmaxf(m, outv[base + jj]);
        float ssum = 0.0f, dy = 0.0f;
#pragma unroll
        for (int jj = 0; jj < L; jj++) {
            float e = __expf(outv[base + jj] - m);
            logits[base + jj] = e;
            ssum += e;
            dy = fmaf(yb[base + jj], outv[base + jj], dy);
        }
        float sinv = 1.0f / ssum;
#pragma unroll
        for (int jj = 0; jj < L; jj++) logits[base + jj] *= sinv;
        loss += m + __logf(ssum) - dy;
        base += L;
    }

    if (lane < 18) out[b * 18 + lane] = logits[lane];
    if (lane == 0) g_loss[b] = loss;
}

// ---------------------------------------------------------------------------
// Kernel 3: deterministic loss reduction
// ---------------------------------------------------------------------------
__global__ void loss_reduce(float* __restrict__ out_loss) {
    __shared__ float s[256];
    float v = 0.0f;
    for (int i = threadIdx.x; i < BB; i += 256) v += g_loss[i];
    s[threadIdx.x] = v;
    __syncthreads();
    for (int o = 128; o > 0; o >>= 1) {
        if (threadIdx.x < o) s[threadIdx.x] += s[threadIdx.x + o];
        __syncthreads();
    }
    if (threadIdx.x == 0) *out_loss = s[0] * (1.0f / (float)BB);
}

// ---------------------------------------------------------------------------
extern "C" void kernel_launch(void* const* d_in, const int* in_sizes, int n_in,
                              void* d_out, int out_size) {
    const int*   x   = (const int*)  d_in[0];
    const float* y   = (const float*)d_in[1];
    const float* emb = (const float*)d_in[2];
    const float* aw  = (const float*)d_in[3];
    const float* ab  = (const float*)d_in[4];
    const float* W0  = (const float*)d_in[5];
    const float* W1  = (const float*)d_in[6];
    const float* W2  = (const float*)d_in[7];
    const float* W3  = (const float*)d_in[8];
    const float* W4  = (const float*)d_in[9];
    float* out = (float*)d_out;

    proj_kernel<<<(VV + 127) / 128, 128>>>(emb, aw, ab, W0, W1, W2, W3, W4);
    main_kernel<<<BB / 4, 128>>>(x, y, out);
    loss_reduce<<<1, 256>>>(out + (out_size - 1));
}

// round 5
// speedup vs baseline: 1.4738x; 1.4738x over previous
#include <cuda_runtime.h>
#include <math.h>

#define BB 4096
#define SS 200
#define DD 64
#define VV 100000
#define ROWF 32   // floats per precomputed row (128B aligned): g[5], q[18], pad

// Static device scratch (allocation-free per harness rules)
__device__ float g_proj[(size_t)VV * ROWF];
__device__ float g_loss[BB];

__device__ __forceinline__ float fast_tanh(float x) {
    float ax = fabsf(x);
    float t  = __expf(-2.0f * ax);
    float r  = __fdividef(1.0f - t, 1.0f + t);
    return copysignf(r, x);
}

// ---------------------------------------------------------------------------
// Kernel 1: per-vocab precompute.
//   23 dot products of emb_table[v] (64-d) against
//   U = [att_w(5); W0(2);W1(4);W2(4);W3(2);W4(6)].
//   Row v of g_proj: [exp(tanh(att+b)) x5, q x18] (+pad to 32).
//   Weights in smem as [d][24] -> 6 broadcast LDS.128 + 23 scalar FFMA per d.
// ---------------------------------------------------------------------------
__global__ void __launch_bounds__(128)
proj_kernel(const float* __restrict__ emb,
            const float* __restrict__ aw,  const float* __restrict__ ab,
            const float* __restrict__ W0,  const float* __restrict__ W1,
            const float* __restrict__ W2,  const float* __restrict__ W3,
            const float* __restrict__ W4) {
    __shared__ float sw[64 * 24];   // [d][j], j in 0..23 (23 = pad)
    __shared__ float sab[5];
    const int tid = threadIdx.x;

    for (int e = tid; e < 64 * 24; e += 128) {
        int d = e / 24, j = e % 24;
        float val = 0.0f;
        if (j < 5) {
            val = aw[j * 64 + d];
        } else if (j < 23) {
            int jq = j - 5;
            const float* Wsrc; int row;
            if      (jq < 2)  { Wsrc = W0; row = jq;      }
            else if (jq < 6)  { Wsrc = W1; row = jq - 2;  }
            else if (jq < 10) { Wsrc = W2; row = jq - 6;  }
            else if (jq < 12) { Wsrc = W3; row = jq - 10; }
            else              { Wsrc = W4; row = jq - 12; }
            val = Wsrc[row * 64 + d];
        }
        sw[e] = val;
    }
    if (tid < 5) sab[tid] = ab[tid];
    __syncthreads();

    const int v = blockIdx.x * 128 + tid;
    if (v >= VV) return;

    float acc[23];
#pragma unroll
    for (int j = 0; j < 23; j++) acc[j] = 0.0f;

    const float4* row = (const float4*)(emb + (size_t)v * DD);
#pragma unroll
    for (int blk = 0; blk < 4; blk++) {
        float4 e0 = row[blk * 4 + 0];
        float4 e1 = row[blk * 4 + 1];
        float4 e2 = row[blk * 4 + 2];
        float4 e3 = row[blk * 4 + 3];
        float es[16] = {e0.x, e0.y, e0.z, e0.w, e1.x, e1.y, e1.z, e1.w,
                        e2.x, e2.y, e2.z, e2.w, e3.x, e3.y, e3.z, e3.w};
#pragma unroll
        for (int dd = 0; dd < 16; dd++) {
            float e = es[dd];
            const float4* wr = (const float4*)(sw + (blk * 16 + dd) * 24);
#pragma unroll
            for (int q = 0; q < 6; q++) {
                float4 w = wr[q];
                acc[q * 4 + 0] = fmaf(e, w.x, acc[q * 4 + 0]);
                acc[q * 4 + 1] = fmaf(e, w.y, acc[q * 4 + 1]);
                acc[q * 4 + 2] = fmaf(e, w.z, acc[q * 4 + 2]);
                if (q < 5)
                    acc[q * 4 + 3] = fmaf(e, w.w, acc[q * 4 + 3]);
            }
        }
    }

    float o[24];
#pragma unroll
    for (int k = 0; k < 5; k++)
        o[k] = __expf(fast_tanh(acc[k] + sab[k]));
#pragma unroll
    for (int j = 0; j < 18; j++) o[5 + j] = acc[5 + j];
    o[23] = 0.0f;

    float4* op = (float4*)(g_proj + (size_t)v * ROWF);
#pragma unroll
    for (int i = 0; i < 6; i++)
        op[i] = make_float4(o[4 * i], o[4 * i + 1], o[4 * i + 2], o[4 * i + 3]);
}

// ---------------------------------------------------------------------------
// Kernel 2: main fused kernel. One warp per batch element.
//   Per chunk of 32 sequence positions:
//     Gather phase: 8-lane groups cooperatively load one 96B row each
//       (coalesced LDG.128, cols 0..5 active), store into per-warp smem
//       with XOR-16B swizzle (conflict-free).
//     Compute phase: lane L consumes row L from smem (6 LDS.128),
//       accumulates lsum[5] + acc[18].
//   Epilogue: warp-reduce, per-group softmax + loss.
// ---------------------------------------------------------------------------
__global__ void __launch_bounds__(128)
main_kernel(const int*   __restrict__ x,
            const float* __restrict__ y,
            float* __restrict__ out) {
    __shared__ float stage_all[4][32 * 32];   // per warp: 32 rows x 128B
    const int lane = threadIdx.x & 31;
    const int warp = threadIdx.x >> 5;
    const int b    = blockIdx.x * 4 + warp;
    float* st = stage_all[warp];

    const int* xb = x + b * SS;
    int idx[7];
#pragma unroll
    for (int c = 0; c < 7; c++) {
        int s = c * 32 + lane;
        idx[c] = (s < SS) ? xb[s] : 0;
    }

    float ls[5] = {0.f, 0.f, 0.f, 0.f, 0.f};
    float acc[18];
#pragma unroll
    for (int j = 0; j < 18; j++) acc[j] = 0.0f;

    const int col = lane & 7;       // 16B column within row (0..7; 0..5 active)
    const int grp = lane >> 3;      // row-within-quad

#pragma unroll
    for (int c = 0; c < 7; c++) {
        // ---- gather phase: 8 quads of rows, 4 rows per LDG ----
#pragma unroll
        for (int t = 0; t < 8; t++) {
            int r = t * 4 + grp;                       // local row 0..31
            int v = __shfl_sync(0xffffffffu, idx[c], r);
            bool act = (col < 6) && (c * 32 + r < SS);
            if (act) {
                float4 val = *(const float4*)(g_proj + (size_t)v * ROWF + col * 4);
                int sc = col ^ (r & 7);
                *(float4*)(st + r * 32 + sc * 4) = val;
            }
        }
        __syncwarp();

        // ---- compute phase: lane consumes row `lane` ----
        if (c * 32 + lane < SS) {
            const float* rp = st + lane * 32;
            int sw = lane & 7;
            float4 r0 = *(const float4*)(rp + ((0 ^ sw) * 4));
            float4 r1 = *(const float4*)(rp + ((1 ^ sw) * 4));
            float4 r2 = *(const float4*)(rp + ((2 ^ sw) * 4));
            float4 r3 = *(const float4*)(rp + ((3 ^ sw) * 4));
            float4 r4 = *(const float4*)(rp + ((4 ^ sw) * 4));
            float4 r5 = *(const float4*)(rp + ((5 ^ sw) * 4));
            ls[0] += r0.x; ls[1] += r0.y; ls[2] += r0.z; ls[3] += r0.w; ls[4] += r1.x;
            acc[0]  = fmaf(r0.x, r1.y, acc[0]);
            acc[1]  = fmaf(r0.x, r1.z, acc[1]);
            acc[2]  = fmaf(r0.y, r1.w, acc[2]);
            acc[3]  = fmaf(r0.y, r2.x, acc[3]);
            acc[4]  = fmaf(r0.y, r2.y, acc[4]);
            acc[5]  = fmaf(r0.y, r2.z, acc[5]);
            acc[6]  = fmaf(r0.z, r2.w, acc[6]);
            acc[7]  = fmaf(r0.z, r3.x, acc[7]);
            acc[8]  = fmaf(r0.z, r3.y, acc[8]);
            acc[9]  = fmaf(r0.z, r3.z, acc[9]);
            acc[10] = fmaf(r0.w, r3.w, acc[10]);
            acc[11] = fmaf(r0.w, r4.x, acc[11]);
            acc[12] = fmaf(r1.x, r4.y, acc[12]);
            acc[13] = fmaf(r1.x, r4.z, acc[13]);
            acc[14] = fmaf(r1.x, r4.w, acc[14]);
            acc[15] = fmaf(r1.x, r5.x, acc[15]);
            acc[16] = fmaf(r1.x, r5.y, acc[16]);
            acc[17] = fmaf(r1.x, r5.z, acc[17]);
        }
        __syncwarp();
    }

    // ---- warp reductions ----
#pragma unroll
    for (int k = 0; k < 5; k++) {
#pragma unroll
        for (int o = 16; o > 0; o >>= 1)
            ls[k] += __shfl_xor_sync(0xffffffffu, ls[k], o);
    }
#pragma unroll
    for (int j = 0; j < 18; j++) {
#pragma unroll
        for (int o = 16; o > 0; o >>= 1)
            acc[j] += __shfl_xor_sync(0xffffffffu, acc[j], o);
    }

    float inv[5];
#pragma unroll
    for (int k = 0; k < 5; k++) inv[k] = 1.0f / ls[k];

    const int kmap[18] = {0,0, 1,1,1,1, 2,2,2,2, 3,3, 4,4,4,4,4,4};
    float outv[18];
#pragma unroll
    for (int j = 0; j < 18; j++) outv[j] = acc[j] * inv[kmap[j]];

    // ---- per-group softmax + cross-entropy loss ----
    const float* yb = y + b * 18;
    const int AL[5] = {2, 4, 4, 2, 6};
    float loss = 0.0f;
    float logits[18];
    int base = 0;
#pragma unroll
    for (int i = 0; i < 5; i++) {
        const int L = AL[i];
        float m = outv[base];
#pragma unroll
        for (int jj = 1; jj < L; jj++) m = fmaxf(m, outv[base + jj]);
        float ssum = 0.0f, dy = 0.0f;
#pragma unroll
        for (int jj = 0; jj < L; jj++) {
            float e = __expf(outv[base + jj] - m);
            logits[base + jj] = e;
            ssum += e;
            dy = fmaf(yb[base + jj], outv[base + jj], dy);
        }
        float sinv = 1.0f / ssum;
#pragma unroll
        for (int jj = 0; jj < L; jj++) logits[base + jj] *= sinv;
        loss += m + __logf(ssum) - dy;
        base += L;
    }

    if (lane < 18) out[b * 18 + lane] = logits[lane];
    if (lane == 0) g_loss[b] = loss;
}

// ---------------------------------------------------------------------------
// Kernel 3: deterministic loss reduction
// ---------------------------------------------------------------------------
__global__ void loss_reduce(float* __restrict__ out_loss) {
    __shared__ float s[256];
    float v = 0.0f;
    for (int i = threadIdx.x; i < BB; i += 256) v += g_loss[i];
    s[threadIdx.x] = v;
    __syncthreads();
    for (int o = 128; o > 0; o >>= 1) {
        if (threadIdx.x < o) s[threadIdx.x] += s[threadIdx.x + o];
        __syncthreads();
    }
    if (threadIdx.x == 0) *out_loss = s[0] * (1.0f / (float)BB);
}

// ---------------------------------------------------------------------------
extern "C" void kernel_launch(void* const* d_in, const int* in_sizes, int n_in,
                              void* d_out, int out_size) {
    const int*   x   = (const int*)  d_in[0];
    const float* y   = (const float*)d_in[1];
    const float* emb = (const float*)d_in[2];
    const float* aw  = (const float*)d_in[3];
    const float* ab  = (const float*)d_in[4];
    const float* W0  = (const float*)d_in[5];
    const float* W1  = (const float*)d_in[6];
    const float* W2  = (const float*)d_in[7];
    const float* W3  = (const float*)d_in[8];
    const float* W4  = (const float*)d_in[9];
    float* out = (float*)d_out;

    proj_kernel<<<(VV + 127) / 128, 128>>>(emb, aw, ab, W0, W1, W2, W3, W4);
    main_kernel<<<BB / 4, 128>>>(x, y, out);
    loss_reduce<<<1, 256>>>(out + (out_size - 1));
}

// round 8
// speedup vs baseline: 1.5343x; 1.0411x over previous
#include <cuda_runtime.h>
#include <math.h>

#define BB 4096
#define SS 200
#define DD 64
#define VV 100000
#define ROWF 32   // floats per precomputed row (128B aligned): g[5], q[18], pad

// Static device scratch (allocation-free per harness rules)
__device__ float g_proj[(size_t)VV * ROWF];
__device__ float g_loss[BB];

__device__ __forceinline__ float fast_tanh(float x) {
    float ax = fabsf(x);
    float t  = __expf(-2.0f * ax);
    float r  = __fdividef(1.0f - t, 1.0f + t);
    return copysignf(r, x);
}

// ---------------------------------------------------------------------------
// Kernel 1: per-vocab precompute, 2 rows per thread.
//   23 dot products of emb_table[v] (64-d) against
//   U = [att_w(5); W0(2);W1(4);W2(4);W3(2);W4(6)].
//   Each weight LDS.128 feeds 2x23 FMAs (two independent vocab rows) ->
//   half the LDS traffic per row, 2x the FFMA ILP vs R4 version.
// ---------------------------------------------------------------------------
__global__ void __launch_bounds__(128)
proj_kernel(const float* __restrict__ emb,
            const float* __restrict__ aw,  const float* __restrict__ ab,
            const float* __restrict__ W0,  const float* __restrict__ W1,
            const float* __restrict__ W2,  const float* __restrict__ W3,
            const float* __restrict__ W4) {
    __shared__ float sw[64 * 24];   // [d][j], j in 0..23 (23 = pad)
    __shared__ float sab[5];
    const int tid = threadIdx.x;

    for (int e = tid; e < 64 * 24; e += 128) {
        int d = e / 24, j = e % 24;
        float val = 0.0f;
        if (j < 5) {
            val = aw[j * 64 + d];
        } else if (j < 23) {
            int jq = j - 5;
            const float* Wsrc; int row;
            if      (jq < 2)  { Wsrc = W0; row = jq;      }
            else if (jq < 6)  { Wsrc = W1; row = jq - 2;  }
            else if (jq < 10) { Wsrc = W2; row = jq - 6;  }
            else if (jq < 12) { Wsrc = W3; row = jq - 10; }
            else              { Wsrc = W4; row = jq - 12; }
            val = Wsrc[row * 64 + d];
        }
        sw[e] = val;
    }
    if (tid < 5) sab[tid] = ab[tid];
    __syncthreads();

    const int v0 = blockIdx.x * 256 + tid;        // always < VV (last block partial)
    const int v1 = v0 + 128;
    const int v1c = (v1 < VV) ? v1 : (VV - 1);    // clamp for safe loads

    float accA[23], accB[23];
#pragma unroll
    for (int j = 0; j < 23; j++) { accA[j] = 0.0f; accB[j] = 0.0f; }

    const float4* rowA = (const float4*)(emb + (size_t)v0 * DD);
    const float4* rowB = (const float4*)(emb + (size_t)v1c * DD);

#pragma unroll
    for (int i = 0; i < 16; i++) {
        float4 ea = rowA[i];
        float4 eb = rowB[i];
        float eas[4] = {ea.x, ea.y, ea.z, ea.w};
        float ebs[4] = {eb.x, eb.y, eb.z, eb.w};
#pragma unroll
        for (int dd = 0; dd < 4; dd++) {
            float fa = eas[dd];
            float fb = ebs[dd];
            const float4* wr = (const float4*)(sw + (i * 4 + dd) * 24);
#pragma unroll
            for (int q = 0; q < 6; q++) {
                float4 w = wr[q];
                accA[q * 4 + 0] = fmaf(fa, w.x, accA[q * 4 + 0]);
                accB[q * 4 + 0] = fmaf(fb, w.x, accB[q * 4 + 0]);
                accA[q * 4 + 1] = fmaf(fa, w.y, accA[q * 4 + 1]);
                accB[q * 4 + 1] = fmaf(fb, w.y, accB[q * 4 + 1]);
                accA[q * 4 + 2] = fmaf(fa, w.z, accA[q * 4 + 2]);
                accB[q * 4 + 2] = fmaf(fb, w.z, accB[q * 4 + 2]);
                if (q < 5) {
                    accA[q * 4 + 3] = fmaf(fa, w.w, accA[q * 4 + 3]);
                    accB[q * 4 + 3] = fmaf(fb, w.w, accB[q * 4 + 3]);
                }
            }
        }
    }

    // Epilogue row A
    {
        float o[24];
#pragma unroll
        for (int k = 0; k < 5; k++) o[k] = __expf(fast_tanh(accA[k] + sab[k]));
#pragma unroll
        for (int j = 0; j < 18; j++) o[5 + j] = accA[5 + j];
        o[23] = 0.0f;
        float4* op = (float4*)(g_proj + (size_t)v0 * ROWF);
#pragma unroll
        for (int i = 0; i < 6; i++)
            op[i] = make_float4(o[4 * i], o[4 * i + 1], o[4 * i + 2], o[4 * i + 3]);
    }
    // Epilogue row B (guarded)
    if (v1 < VV) {
        float o[24];
#pragma unroll
        for (int k = 0; k < 5; k++) o[k] = __expf(fast_tanh(accB[k] + sab[k]));
#pragma unroll
        for (int j = 0; j < 18; j++) o[5 + j] = accB[5 + j];
        o[23] = 0.0f;
        float4* op = (float4*)(g_proj + (size_t)v1 * ROWF);
#pragma unroll
        for (int i = 0; i < 6; i++)
            op[i] = make_float4(o[4 * i], o[4 * i + 1], o[4 * i + 2], o[4 * i + 3]);
    }
}

// ---------------------------------------------------------------------------
// Kernel 2: main fused kernel. TWO warps per batch element (100 seq rows
// each, 4 chunks of 32). Indices staged in smem (no shuffles in gather);
// next chunk's 8 gather LDGs prefetched into registers during current
// chunk's compute. Warp partials (ls[5], acc[18]) combined via smem.
// ---------------------------------------------------------------------------
__global__ void __launch_bounds__(128)
main_kernel(const int*   __restrict__ x,
            const float* __restrict__ y,
            float* __restrict__ out) {
    __shared__ float stage_all[4][32 * 32];   // per warp: 32 rows x 128B
    __shared__ int   sidx[4][128];            // per warp: chunk indices
    __shared__ float partial[2][24];          // half=1 partials per b-in-block

    const int lane = threadIdx.x & 31;
    const int warp = threadIdx.x >> 5;
    const int bi   = warp >> 1;               // b within block (0..1)
    const int half = warp & 1;                // seq half (0..1)
    const int b    = blockIdx.x * 2 + bi;
    float* st = stage_all[warp];
    int*   si = sidx[warp];

    // Stage this warp's 100 indices (pad to 128 with 0)
    const int* xb = x + b * SS + half * 100;
#pragma unroll
    for (int c = 0; c < 4; c++) {
        int loc = c * 32 + lane;
        si[loc] = (loc < 100) ? xb[loc] : 0;
    }
    __syncwarp();

    float ls[5] = {0.f, 0.f, 0.f, 0.f, 0.f};
    float acc[18];
#pragma unroll
    for (int j = 0; j < 18; j++) acc[j] = 0.0f;

    const int col = lane & 7;       // 16B column within row (0..7; 0..5 active)
    const int grp = lane >> 3;      // row-within-quad

    float4 buf[8];                  // prefetched gather values (8 rows/quad slots)
    bool   bact[8];

    // Prefetch chunk 0
#pragma unroll
    for (int t = 0; t < 8; t++) {
        int r = t * 4 + grp;
        int v = si[r];
        bact[t] = (col < 6) && (r < 100);
        buf[t] = bact[t] ? *(const float4*)(g_proj + (size_t)v * ROWF + col * 4)
                         : make_float4(0.f, 0.f, 0.f, 0.f);
    }

#pragma unroll
    for (int c = 0; c < 4; c++) {
        // Store prefetched chunk into swizzled smem
#pragma unroll
        for (int t = 0; t < 8; t++) {
            int r = t * 4 + grp;
            if (bact[t]) {
                int sc = col ^ (r & 7);
                *(float4*)(st + r * 32 + sc * 4) = buf[t];
            }
        }
        __syncwarp();

        // Prefetch next chunk (LDGs in flight during compute below)
        if (c < 3) {
#pragma unroll
            for (int t = 0; t < 8; t++) {
                int r  = t * 4 + grp;
                int gl = (c + 1) * 32 + r;
                int v  = si[gl < 128 ? gl : 0];
                bact[t] = (col < 6) && (gl < 100);
                buf[t] = bact[t] ? *(const float4*)(g_proj + (size_t)v * ROWF + col * 4)
                                 : make_float4(0.f, 0.f, 0.f, 0.f);
            }
        }

        // Compute: lane consumes row `lane` of current chunk
        if (c * 32 + lane < 100) {
            const float* rp = st + lane * 32;
            int sw = lane & 7;
            float4 r0 = *(const float4*)(rp + ((0 ^ sw) * 4));
            float4 r1 = *(const float4*)(rp + ((1 ^ sw) * 4));
            float4 r2 = *(const float4*)(rp + ((2 ^ sw) * 4));
            float4 r3 = *(const float4*)(rp + ((3 ^ sw) * 4));
            float4 r4 = *(const float4*)(rp + ((4 ^ sw) * 4));
            float4 r5 = *(const float4*)(rp + ((5 ^ sw) * 4));
            ls[0] += r0.x; ls[1] += r0.y; ls[2] += r0.z; ls[3] += r0.w; ls[4] += r1.x;
            acc[0]  = fmaf(r0.x, r1.y, acc[0]);
            acc[1]  = fmaf(r0.x, r1.z, acc[1]);
            acc[2]  = fmaf(r0.y, r1.w, acc[2]);
            acc[3]  = fmaf(r0.y, r2.x, acc[3]);
            acc[4]  = fmaf(r0.y, r2.y, acc[4]);
            acc[5]  = fmaf(r0.y, r2.z, acc[5]);
            acc[6]  = fmaf(r0.z, r2.w, acc[6]);
            acc[7]  = fmaf(r0.z, r3.x, acc[7]);
            acc[8]  = fmaf(r0.z, r3.y, acc[8]);
            acc[9]  = fmaf(r0.z, r3.z, acc[9]);
            acc[10] = fmaf(r0.w, r3.w, acc[10]);
            acc[11] = fmaf(r0.w, r4.x, acc[11]);
            acc[12] = fmaf(r1.x, r4.y, acc[12]);
            acc[13] = fmaf(r1.x, r4.z, acc[13]);
            acc[14] = fmaf(r1.x, r4.w, acc[14]);
            acc[15] = fmaf(r1.x, r5.x, acc[15]);
            acc[16] = fmaf(r1.x, r5.y, acc[16]);
            acc[17] = fmaf(r1.x, r5.z, acc[17]);
        }
        __syncwarp();
    }

    // ---- intra-warp reductions ----
#pragma unroll
    for (int k = 0; k < 5; k++) {
#pragma unroll
        for (int o = 16; o > 0; o >>= 1)
            ls[k] += __shfl_xor_sync(0xffffffffu, ls[k], o);
    }
#pragma unroll
    for (int j = 0; j < 18; j++) {
#pragma unroll
        for (int o = 16; o > 0; o >>= 1)
            acc[j] += __shfl_xor_sync(0xffffffffu, acc[j], o);
    }

    // ---- combine halves via smem ----
    if (half == 1) {
        if (lane < 5)  partial[bi][lane] = ls[lane];
        if (lane < 18) partial[bi][5 + lane] = acc[lane];
    }
    __syncthreads();
    if (half == 1) return;

#pragma unroll
    for (int k = 0; k < 5; k++) ls[k] += partial[bi][k];
#pragma unroll
    for (int j = 0; j < 18; j++) acc[j] += partial[bi][5 + j];

    float inv[5];
#pragma unroll
    for (int k = 0; k < 5; k++) inv[k] = 1.0f / ls[k];

    const int kmap[18] = {0,0, 1,1,1,1, 2,2,2,2, 3,3, 4,4,4,4,4,4};
    float outv[18];
#pragma unroll
    for (int j = 0; j < 18; j++) outv[j] = acc[j] * inv[kmap[j]];

    // ---- per-group softmax + cross-entropy loss ----
    const float* yb = y + b * 18;
    const int AL[5] = {2, 4, 4, 2, 6};
    float loss = 0.0f;
    float logits[18];
    int base = 0;
#pragma unroll
    for (int i = 0; i < 5; i++) {
        const int L = AL[i];
        float m = outv[base];
#pragma unroll
        for (int jj = 1; jj < L; jj++) m = fmaxf(m, outv[base + jj]);
        float ssum = 0.0f, dy = 0.0f;
#pragma unroll
        for (int jj = 0; jj < L; jj++) {
            float e = __expf(outv[base + jj] - m);
            logits[base + jj] = e;
            ssum += e;
            dy = fmaf(yb[base + jj], outv[base + jj], dy);
        }
        float sinv = 1.0f / ssum;
#pragma unroll
        for (int jj = 0; jj < L; jj++) logits[base + jj] *= sinv;
        loss += m + __logf(ssum) - dy;
        base += L;
    }

    if (lane < 18) out[b * 18 + lane] = logits[lane];
    if (lane == 0) g_loss[b] = loss;
}

// ---------------------------------------------------------------------------
// Kernel 3: deterministic loss reduction
// ---------------------------------------------------------------------------
__global__ void loss_reduce(float* __restrict__ out_loss) {
    __shared__ float s[256];
    float v = 0.0f;
    for (int i = threadIdx.x; i < BB; i += 256) v += g_loss[i];
    s[threadIdx.x] = v;
    __syncthreads();
    for (int o = 128; o > 0; o >>= 1) {
        if (threadIdx.x < o) s[threadIdx.x] += s[threadIdx.x + o];
        __syncthreads();
    }
    if (threadIdx.x == 0) *out_loss = s[0] * (1.0f / (float)BB);
}

// ---------------------------------------------------------------------------
extern "C" void kernel_launch(void* const* d_in, const int* in_sizes, int n_in,
                              void* d_out, int out_size) {
    const int*   x   = (const int*)  d_in[0];
    const float* y   = (const float*)d_in[1];
    const float* emb = (const float*)d_in[2];
    const float* aw  = (const float*)d_in[3];
    const float* ab  = (const float*)d_in[4];
    const float* W0  = (const float*)d_in[5];
    const float* W1  = (const float*)d_in[6];
    const float* W2  = (const float*)d_in[7];
    const float* W3  = (const float*)d_in[8];
    const float* W4  = (const float*)d_in[9];
    float* out = (float*)d_out;

    proj_kernel<<<(VV + 255) / 256, 128>>>(emb, aw, ab, W0, W1, W2, W3, W4);
    main_kernel<<<BB / 2, 128>>>(x, y, out);
    loss_reduce<<<1, 256>>>(out + (out_size - 1));
}